// round 2
// baseline (speedup 1.0000x reference)
#include <cuda_runtime.h>
#include <math.h>

#define SIMS 2048
#define NB   256
#define MID  512
#define G    128     // persistent CTAs (<= SM count, co-resident)
#define TPB  256
#define RPC  16      // rows per CTA = SIMS/G

// ---------------- device scratch (no allocation allowed) ----------------
__device__ float g_y[SIMS * MID];       // y = xs@w1 + b1 - corr   (4 MB)
__device__ float g_ps[NB * SIMS];       // ps history [t][s]       (2 MB)
__device__ float g_w1T[MID * NB];       // w1T[j][c] = w1[c][j]
__device__ float g_w2T[NB * MID];       // w2T[c][j] = w2[j][c]
__device__ float g_common[MID];         // shared common vector
__device__ int   g_winner[NB * NB];     // [t][c] = max s with ids[s,t]==c, else -1
__device__ int   g_firstw[NB];          // first step column c is written (1<<30 if never)
__device__ int   g_newlist[NB];         // columns grouped by first-write step
__device__ int   g_newstart[NB + 1];
__device__ unsigned g_barcnt;
__device__ unsigned g_bargen;

// ---------------- grid barrier (sense-reversing, graph-safe) ----------------
__device__ __forceinline__ void grid_barrier() {
    __syncthreads();
    if (threadIdx.x == 0) {
        __threadfence();
        unsigned gen = *((volatile unsigned*)&g_bargen);
        unsigned a = atomicAdd(&g_barcnt, 1u);
        if (a == (unsigned)(G - 1)) {
            g_barcnt = 0u;
            __threadfence();
            atomicAdd(&g_bargen, 1u);
        } else {
            while (*((volatile unsigned*)&g_bargen) == gen) { }
            __threadfence();
        }
    }
    __syncthreads();
}

// ---------------- init kernels ----------------
__global__ void k_init1(const float* __restrict__ w1, const float* __restrict__ w2) {
    int idx = blockIdx.x * blockDim.x + threadIdx.x;   // 131072 threads
    if (idx < NB * NB) g_winner[idx] = -1;
    {   // w1T[j*NB + c] = w1[c*MID + j]
        int j = idx >> 8, c = idx & (NB - 1);
        g_w1T[idx] = w1[c * MID + j];
    }
    {   // w2T[c*MID + j] = w2[j*NB + c]
        int c = idx >> 9, j = idx & (MID - 1);
        g_w2T[idx] = w2[j * NB + c];
    }
    if (idx < MID) g_common[idx] = 0.f;
}

__global__ void k_init2(const int* __restrict__ ids) {
    int idx = blockIdx.x * blockDim.x + threadIdx.x;   // SIMS*NB threads; idx = s*256 + t
    int s = idx >> 8;
    int t = idx & (NB - 1);
    int c = ids[idx];
    atomicMax(&g_winner[t * NB + c], s);
}

__global__ void k_init3() {
    __shared__ int fw[NB];
    int c = threadIdx.x;
    int f = 1 << 30;
    for (int t = 0; t < NB; t++) {
        if (g_winner[t * NB + c] >= 0) { f = t; break; }
    }
    g_firstw[c] = f;
    fw[c] = f;
    __syncthreads();
    if (c == 0) {   // deterministic single-thread build of first-write lists
        int pos = 0;
        for (int t = 0; t < NB; t++) {
            g_newstart[t] = pos;
            for (int cc = 0; cc < NB; cc++)
                if (fw[cc] == t) g_newlist[pos++] = cc;
        }
        g_newstart[NB] = pos;
    }
}

// base = xs @ w1 + b1
__global__ void __launch_bounds__(TPB) k_base(const float* __restrict__ xs,
                                              const float* __restrict__ w1,
                                              const float* __restrict__ b1) {
    __shared__ float xsS[RPC * NB];
    int tid = threadIdx.x;
    int row0 = blockIdx.x * RPC;
    for (int i = tid; i < RPC * NB; i += TPB) xsS[i] = xs[row0 * NB + i];
    __syncthreads();

    float acc0[RPC], acc1[RPC];
#pragma unroll
    for (int r = 0; r < RPC; r++) { acc0[r] = 0.f; acc1[r] = 0.f; }
    int j0 = tid, j1 = tid + TPB;
    for (int c = 0; c < NB; c++) {
        float wa = w1[c * MID + j0];
        float wb = w1[c * MID + j1];
#pragma unroll
        for (int r = 0; r < RPC; r++) {
            float xv = xsS[r * NB + c];
            acc0[r] += xv * wa;
            acc1[r] += xv * wb;
        }
    }
    float bb0 = b1[j0], bb1 = b1[j1];
    for (int r = 0; r < RPC; r++) {
        g_y[(row0 + r) * MID + j0] = acc0[r] + bb0;
        g_y[(row0 + r) * MID + j1] = acc1[r] + bb1;
    }
}

// ---------------- main persistent kernel ----------------
__global__ void __launch_bounds__(TPB) k_main(const float* __restrict__ xs,
                                              const int* __restrict__ ids,
                                              const float* __restrict__ w1,
                                              const float* __restrict__ gamma,
                                              const float* __restrict__ beta,
                                              const float* __restrict__ b2,
                                              float* __restrict__ out) {
    extern __shared__ float sm[];
    float* yS      = sm;                    // RPC*MID
    float* xsS     = yS + RPC * MID;        // RPC*NB
    float* commonS = xsS + RPC * NB;        // MID
    float* uS      = commonS + MID;         // NB
    float* gammaS  = uS + NB;               // MID
    float* betaS   = gammaS + MID;          // MID
    float* partS   = betaS + MID;           // TPB
    int*   idsS    = (int*)(partS + TPB);   // RPC*NB
    int*   fwS     = idsS + RPC * NB;       // NB

    const int tid  = threadIdx.x;
    const int b    = blockIdx.x;
    const int row0 = b * RPC;
    const int lane = tid & 31;
    const int wid  = tid >> 5;

    for (int i = tid; i < RPC * MID; i += TPB) yS[i] = g_y[row0 * MID + i];
    for (int i = tid; i < RPC * NB; i += TPB) {
        xsS[i]  = xs[row0 * NB + i];
        idsS[i] = ids[row0 * NB + i];
    }
    for (int i = tid; i < MID; i += TPB) { gammaS[i] = gamma[i]; betaS[i] = beta[i]; }
    if (tid < NB) { uS[tid] = 0.f; fwS[tid] = g_firstw[tid]; }
    __syncthreads();

    for (int t = 0; t < NB; t++) {
        // ---- fetch common (produced by phase B of step t-1) ----
        commonS[tid]       = g_common[tid];
        commonS[tid + TPB] = g_common[tid + TPB];
        __syncthreads();

        // ---- phase A: forward for this CTA's rows (1 warp -> 2 rows) ----
#pragma unroll
        for (int rr = 0; rr < 2; rr++) {
            const int rl = wid * 2 + rr;
            float gv[16];
            float ssum = 0.f;
#pragma unroll
            for (int k4 = 0; k4 < 4; k4++) {
                int j4 = k4 * 128 + lane * 4;
                float4 yv = *(const float4*)&yS[rl * MID + j4];
                float4 cv = *(const float4*)&commonS[j4];
                float p0 = yv.x + cv.x, p1 = yv.y + cv.y;
                float p2 = yv.z + cv.z, p3 = yv.w + cv.w;
                float e0 = 0.5f * p0 * (1.f + erff(p0 * 0.7071067811865476f));
                float e1 = 0.5f * p1 * (1.f + erff(p1 * 0.7071067811865476f));
                float e2 = 0.5f * p2 * (1.f + erff(p2 * 0.7071067811865476f));
                float e3 = 0.5f * p3 * (1.f + erff(p3 * 0.7071067811865476f));
                gv[k4 * 4 + 0] = e0; gv[k4 * 4 + 1] = e1;
                gv[k4 * 4 + 2] = e2; gv[k4 * 4 + 3] = e3;
                ssum += (e0 + e1) + (e2 + e3);
            }
#pragma unroll
            for (int off = 16; off; off >>= 1)
                ssum += __shfl_xor_sync(0xffffffffu, ssum, off);
            float mu = ssum * (1.f / 512.f);
            float vs = 0.f;
#pragma unroll
            for (int k = 0; k < 16; k++) { float d = gv[k] - mu; vs += d * d; }
#pragma unroll
            for (int off = 16; off; off >>= 1)
                vs += __shfl_xor_sync(0xffffffffu, vs, off);
            float inv = rsqrtf(vs * (1.f / 512.f) + 1e-5f);

            int col = idsS[rl * NB + t];
            const float* w2r = g_w2T + col * MID;
            float dot = 0.f;
#pragma unroll
            for (int k4 = 0; k4 < 4; k4++) {
                int j4 = k4 * 128 + lane * 4;
                float4 gm = *(const float4*)&gammaS[j4];
                float4 bt = *(const float4*)&betaS[j4];
                float4 wv = *(const float4*)&w2r[j4];
                dot += ((gv[k4 * 4 + 0] - mu) * inv * gm.x + bt.x) * wv.x;
                dot += ((gv[k4 * 4 + 1] - mu) * inv * gm.y + bt.y) * wv.y;
                dot += ((gv[k4 * 4 + 2] - mu) * inv * gm.z + bt.z) * wv.z;
                dot += ((gv[k4 * 4 + 3] - mu) * inv * gm.w + bt.w) * wv.w;
            }
#pragma unroll
            for (int off = 16; off; off >>= 1)
                dot += __shfl_xor_sync(0xffffffffu, dot, off);
            if (lane == 0) {
                float z = dot + b2[col];
                g_ps[t * SIMS + row0 + rl] = 1.f / (1.f + expf(-z));
            }
        }
        grid_barrier();

        // ---- phase B: update u, common slice, first-write corrections ----
        {
            int w = g_winner[t * NB + tid];
            if (w >= 0) uS[tid] = g_ps[t * SIMS + w];
        }
        __syncthreads();
        {
            int jj = tid & 3;          // 4 j's owned by this CTA
            int cc = tid >> 2;         // 64 c-chunks of 4
            int j  = b * 4 + jj;
            const float* w1Tj = g_w1T + j * NB + cc * 4;
            const float* up   = uS + cc * 4;
            partS[jj * 64 + cc] = up[0] * w1Tj[0] + up[1] * w1Tj[1]
                                + up[2] * w1Tj[2] + up[3] * w1Tj[3];
        }
        __syncthreads();
        if (tid < 4) {
            float s2 = 0.f;
#pragma unroll
            for (int k = 0; k < 64; k++) s2 += partS[tid * 64 + k];
            g_common[b * 4 + tid] = s2;
        }
        const int st = g_newstart[t], en = g_newstart[t + 1];
        for (int i = st; i < en; i++) {
            int c = g_newlist[i];
            float wa = w1[c * MID + tid];
            float wb = w1[c * MID + tid + TPB];
#pragma unroll
            for (int rl = 0; rl < RPC; rl++) {
                float xv = xsS[rl * NB + c];
                yS[rl * MID + tid]       -= xv * wa;
                yS[rl * MID + tid + TPB] -= xv * wb;
            }
        }
        grid_barrier();
    }

    // ---- write final probs: u[c] if ever written else xs ----
    for (int i = tid; i < RPC * NB; i += TPB) {
        int c  = i & (NB - 1);
        int rl = i >> 8;
        float v = (fwS[c] < NB) ? uS[c] : xsS[i];
        out[(row0 + rl) * NB + c] = v;
    }
}

// ---------------- launch ----------------
extern "C" void kernel_launch(void* const* d_in, const int* in_sizes, int n_in,
                              void* d_out, int out_size) {
    const float* xs    = (const float*)d_in[0];
    const int*   ids   = (const int*)d_in[1];
    const float* w1    = (const float*)d_in[2];
    const float* b1    = (const float*)d_in[3];
    const float* gamma = (const float*)d_in[4];
    const float* beta  = (const float*)d_in[5];
    const float* w2    = (const float*)d_in[6];
    const float* b2    = (const float*)d_in[7];
    float* out = (float*)d_out;

    k_init1<<<512, 256>>>(w1, w2);
    k_init2<<<SIMS * NB / 256, 256>>>(ids);
    k_init3<<<1, 256>>>();
    k_base<<<G, TPB>>>(xs, w1, b1);

    const int smem_main = (RPC * MID + RPC * NB + MID + NB + MID + MID + TPB) * 4
                        + (RPC * NB + NB) * 4;
    cudaFuncSetAttribute(k_main, cudaFuncAttributeMaxDynamicSharedMemorySize, smem_main);
    k_main<<<G, TPB, smem_main>>>(xs, ids, w1, gamma, beta, b2, out);
}

// round 3
// speedup vs baseline: 1.9938x; 1.9938x over previous
#include <cuda_runtime.h>
#include <math.h>

#define SIMS 2048
#define NB   256
#define MID  512
#define G    128     // persistent CTAs (1 per SM, co-resident on 148 SMs)
#define TPB  512     // 16 warps -> 1 row per warp
#define RPC  16      // rows per CTA = SIMS/G

// ---------------- device scratch (no allocation allowed) ----------------
__device__ __align__(16) float g_y [SIMS * MID];   // full base = xs@w1+b1
__device__ __align__(16) float g_y2[SIMS * MID];   // base minus fw==0 columns
__device__ __align__(16) float g_w1T[MID * NB];    // w1T[j][c] = w1[c][j]
__device__ __align__(16) float g_w2g[NB * MID];    // w2g[c][j] = gamma[j]*w2[j][c]
__device__ __align__(16) float g_u[NB];            // current per-column value
__device__ __align__(16) float g_common[MID];
__device__ float g_Ac[NB];                         // sum_j gamma[j]*w2[j][c]
__device__ float g_bc[NB];                         // sum_j beta[j]*w2[j][c] + b2[c]
__device__ int   g_winner[NB * NB];                // [t][c] = max s with ids[s,t]==c
__device__ int   g_fw[NB];                         // first-write step of column c
__device__ int   g_idsw[SIMS * NB];                // c | (winner-bit << 8)
__device__ int   g_newlist[NB];
__device__ int   g_newstart[NB + 1];
__device__ unsigned g_cnt;

// ---------------- grid barrier (monotonic counter) ----------------
__device__ __forceinline__ void gbar(unsigned &tgt) {
    __syncthreads();
    if (threadIdx.x == 0) {
        __threadfence();
        atomicAdd(&g_cnt, 1u);
        while (*(volatile unsigned*)&g_cnt < tgt) { }
        __threadfence();
    }
    __syncthreads();
    tgt += G;
}

// ---------------- fast exact-erf GELU (A&S 7.1.26, |err|<=1.5e-7) --------
__device__ __forceinline__ float gelu_f(float x) {
    float z  = 0.70710678118654752f * x;
    float az = fabsf(z);
    float t  = __fdividef(1.0f, fmaf(0.3275911f, az, 1.0f));
    float p  = t * fmaf(t, fmaf(t, fmaf(t, fmaf(t, 1.061405429f, -1.453152027f),
                                        1.421413741f), -0.284496736f), 0.254829592f);
    float ex = __expf(-z * z);
    float E  = fmaf(-p, ex, 1.0f);
    float e  = copysignf(E, x);
    float hx = 0.5f * x;
    return fmaf(hx, e, hx);
}

// ---------------- init kernels ----------------
__global__ void k_init1(const float* __restrict__ w1,
                        const float* __restrict__ w2,
                        const float* __restrict__ gamma) {
    int idx = blockIdx.x * blockDim.x + threadIdx.x;   // 131072 threads
    if (idx < NB * NB) g_winner[idx] = -1;
    {   // w1T[j*NB + c] = w1[c*MID + j]
        int j = idx >> 8, c = idx & (NB - 1);
        g_w1T[idx] = w1[c * MID + j];
    }
    {   // w2g[c*MID + j] = gamma[j] * w2[j*NB + c]
        int c = idx >> 9, j = idx & (MID - 1);
        g_w2g[idx] = gamma[j] * w2[j * NB + c];
    }
    if (idx < MID) g_common[idx] = 0.f;
    if (idx < NB)  g_u[idx] = 0.f;
    if (idx == 0)  g_cnt = 0u;
}

__global__ void k_init2(const int* __restrict__ ids) {
    int idx = blockIdx.x * blockDim.x + threadIdx.x;   // idx = s*256 + t
    int s = idx >> 8;
    int t = idx & (NB - 1);
    int c = ids[idx];
    atomicMax(&g_winner[t * NB + c], s);
}

__global__ void k_init3() {
    __shared__ int fw[NB];
    __shared__ int cnt[NB];
    __shared__ int start[NB + 1];
    __shared__ int offs[NB];
    int c = threadIdx.x;                 // 256 threads
    cnt[c] = 0;
    int f = 1 << 30;
    for (int t = 0; t < NB; t++)
        if (g_winner[t * NB + c] >= 0) { f = t; break; }
    g_fw[c] = f;
    fw[c] = f;
    __syncthreads();
    if (f < NB) atomicAdd(&cnt[f], 1);
    __syncthreads();
    if (c == 0) {
        int pos = 0;
        for (int t = 0; t < NB; t++) { start[t] = pos; pos += cnt[t]; }
        start[NB] = pos;
    }
    __syncthreads();
    g_newstart[c] = start[c];
    if (c == 0) g_newstart[NB] = start[NB];
    offs[c] = start[c];
    __syncthreads();
    if (f < NB) {
        int p = atomicAdd(&offs[f], 1);
        g_newlist[p] = c;
    }
}

__global__ void k_init4(const int* __restrict__ ids) {
    int idx = blockIdx.x * blockDim.x + threadIdx.x;   // idx = s*256 + t
    int s = idx >> 8;
    int t = idx & (NB - 1);
    int c = ids[idx];
    int win = (g_winner[t * NB + c] == s) ? 256 : 0;
    g_idsw[idx] = c | win;
}

__global__ void k_init5(const float* __restrict__ w2,
                        const float* __restrict__ gamma,
                        const float* __restrict__ beta,
                        const float* __restrict__ b2) {
    __shared__ float sa[4], sb[4];
    int c = blockIdx.x;
    int tid = threadIdx.x;               // 128 threads
    float a = 0.f, bs = 0.f;
    for (int j = tid; j < MID; j += 128) {
        float w = w2[j * NB + c];
        a  = fmaf(gamma[j], w, a);
        bs = fmaf(beta[j],  w, bs);
    }
#pragma unroll
    for (int off = 16; off; off >>= 1) {
        a  += __shfl_xor_sync(0xffffffffu, a,  off);
        bs += __shfl_xor_sync(0xffffffffu, bs, off);
    }
    if ((tid & 31) == 0) { sa[tid >> 5] = a; sb[tid >> 5] = bs; }
    __syncthreads();
    if (tid == 0) {
        g_Ac[c] = sa[0] + sa[1] + sa[2] + sa[3];
        g_bc[c] = sb[0] + sb[1] + sb[2] + sb[3] + b2[c];
    }
}

// base = xs @ w1 + b1 ; y2 = b1 + sum over columns with fw>=1
__global__ void __launch_bounds__(TPB) k_base(const float* __restrict__ xs,
                                              const float* __restrict__ w1,
                                              const float* __restrict__ b1) {
    __shared__ float xsS[RPC * NB];
    int tid = threadIdx.x;               // j = tid, 512 threads
    int row0 = blockIdx.x * RPC;
    for (int i = tid; i < RPC * NB; i += TPB) xsS[i] = xs[row0 * NB + i];
    __syncthreads();

    float acc[RPC];
#pragma unroll
    for (int r = 0; r < RPC; r++) acc[r] = 0.f;
#pragma unroll 4
    for (int c = 0; c < NB; c++) {
        float w = w1[c * MID + tid];
#pragma unroll
        for (int r = 0; r < RPC; r++)
            acc[r] = fmaf(xsS[r * NB + c], w, acc[r]);
    }
    float bb = b1[tid];
#pragma unroll
    for (int r = 0; r < RPC; r++)
        g_y[(row0 + r) * MID + tid] = acc[r] + bb;

    // y2: b1 + columns NOT first-written at step 0 (usually ~none)
    float y2a[RPC];
#pragma unroll
    for (int r = 0; r < RPC; r++) y2a[r] = bb;
    int st = g_newstart[1], en = g_newstart[NB];
    for (int i = st; i < en; i++) {
        int c = g_newlist[i];
        float w = w1[c * MID + tid];
#pragma unroll
        for (int r = 0; r < RPC; r++)
            y2a[r] = fmaf(xsS[r * NB + c], w, y2a[r]);
    }
#pragma unroll
    for (int r = 0; r < RPC; r++)
        g_y2[(row0 + r) * MID + tid] = y2a[r];
}

// ---------------- main persistent kernel ----------------
__global__ void __launch_bounds__(TPB) k_main(const float* __restrict__ xs,
                                              const float* __restrict__ w1,
                                              float* __restrict__ out) {
    extern __shared__ float sm[];
    float* yS    = sm;                        // 8192
    float* xsS   = yS + RPC * MID;            // 4096
    float* cS    = xsS + RPC * NB;            // 512
    float* AcS   = cS + MID;                  // 256
    float* bcS   = AcS + NB;                  // 256
    float* uS    = bcS + NB;                  // 256
    float* partS = uS + NB;                   // 16
    int*   idswS = (int*)(partS + 16);        // 4096
    int*   nsS   = idswS + RPC * NB;          // 257
    int*   fwS   = nsS + (NB + 1);            // 256

    const int tid  = threadIdx.x;
    const int b    = blockIdx.x;
    const int row0 = b * RPC;
    const int lane = tid & 31;
    const int wid  = tid >> 5;                // row within CTA (0..15)

    for (int i = tid; i < RPC * MID; i += TPB) yS[i] = g_y[row0 * MID + i];
    for (int i = tid; i < RPC * NB; i += TPB) {
        xsS[i]   = xs[row0 * NB + i];
        idswS[i] = g_idsw[row0 * NB + i];
    }
    if (tid < NB) {
        AcS[tid] = g_Ac[tid];
        bcS[tid] = g_bc[tid];
        fwS[tid] = g_fw[tid];
    }
    if (tid <= NB) nsS[tid] = g_newstart[tid];
    __syncthreads();

    unsigned tgt = G;

    for (int t = 0; t < NB; t++) {
        cS[tid] = g_common[tid];
        __syncthreads();

        // ---- phase A: one row per warp ----
        {
            const int rl = wid;
            int info = idswS[rl * NB + t];
            int col  = info & 255;
            const float4* y4 = (const float4*)(yS + rl * MID);
            const float4* c4 = (const float4*)cS;
            const float4* w4 = (const float4*)(g_w2g + (size_t)col * MID);
            float s = 0.f, q = 0.f, d = 0.f;
#pragma unroll
            for (int k = 0; k < 4; k++) {
                float4 yv = y4[k * 32 + lane];
                float4 cv = c4[k * 32 + lane];
                float4 wv = w4[k * 32 + lane];
                float g0 = gelu_f(yv.x + cv.x);
                float g1 = gelu_f(yv.y + cv.y);
                float g2 = gelu_f(yv.z + cv.z);
                float g3 = gelu_f(yv.w + cv.w);
                s += (g0 + g1) + (g2 + g3);
                q = fmaf(g0, g0, q); q = fmaf(g1, g1, q);
                q = fmaf(g2, g2, q); q = fmaf(g3, g3, q);
                d = fmaf(g0, wv.x, d); d = fmaf(g1, wv.y, d);
                d = fmaf(g2, wv.z, d); d = fmaf(g3, wv.w, d);
            }
#pragma unroll
            for (int off = 16; off; off >>= 1) {
                s += __shfl_xor_sync(0xffffffffu, s, off);
                q += __shfl_xor_sync(0xffffffffu, q, off);
                d += __shfl_xor_sync(0xffffffffu, d, off);
            }
            if (lane == 0 && (info & 256)) {
                float mu  = s * (1.f / 512.f);
                float var = fmaf(-mu, mu, q * (1.f / 512.f));
                float inv = rsqrtf(var + 1e-5f);
                float logit = fmaf(inv, fmaf(-mu, AcS[col], d), bcS[col]);
                float p = __fdividef(1.f, 1.f + __expf(-logit));
                g_u[col] = p;
            }
        }
        gbar(tgt);   // barrier 1: all g_u writes for step t visible

        // ---- phase B: common slice (4 j's per CTA) + corrections ----
        {
            int jj = tid >> 7;                 // 0..3
            int cc = tid & 127;                // 0..127 -> 2 columns each
            float2 uv = ((const float2*)g_u)[cc];
            float2 wv = *(const float2*)(g_w1T + (size_t)(b * 4 + jj) * NB + cc * 2);
            float sv = fmaf(uv.x, wv.x, uv.y * wv.y);
#pragma unroll
            for (int off = 16; off; off >>= 1)
                sv += __shfl_xor_sync(0xffffffffu, sv, off);
            if (lane == 0) partS[wid] = sv;
            __syncthreads();
            if (tid < 4)
                g_common[b * 4 + tid] = (partS[tid * 4 + 0] + partS[tid * 4 + 1])
                                      + (partS[tid * 4 + 2] + partS[tid * 4 + 3]);
        }
        if (t == 0) {
            // bulk first-write correction (precomputed by k_base)
            for (int i = tid; i < RPC * MID; i += TPB)
                yS[i] = g_y2[row0 * MID + i];
        } else {
            int st = nsS[t], en = nsS[t + 1];
            for (int i = st; i < en; i++) {
                int c = g_newlist[i];
                float w = w1[c * MID + tid];
#pragma unroll
                for (int rl = 0; rl < RPC; rl++)
                    yS[rl * MID + tid] -= xsS[rl * NB + c] * w;
            }
        }
        gbar(tgt);   // barrier 2: g_common complete
    }

    // ---- output: u[c] if ever written else xs ----
    if (tid < NB) uS[tid] = g_u[tid];
    __syncthreads();
    for (int i = tid; i < RPC * NB; i += TPB) {
        int c  = i & (NB - 1);
        int rl = i >> 8;
        float v = (fwS[c] < NB) ? uS[c] : xsS[i];
        out[(row0 + rl) * NB + c] = v;
    }
}

// ---------------- launch ----------------
extern "C" void kernel_launch(void* const* d_in, const int* in_sizes, int n_in,
                              void* d_out, int out_size) {
    const float* xs    = (const float*)d_in[0];
    const int*   ids   = (const int*)d_in[1];
    const float* w1    = (const float*)d_in[2];
    const float* b1    = (const float*)d_in[3];
    const float* gamma = (const float*)d_in[4];
    const float* beta  = (const float*)d_in[5];
    const float* w2    = (const float*)d_in[6];
    const float* b2    = (const float*)d_in[7];
    float* out = (float*)d_out;

    k_init1<<<512, 256>>>(w1, w2, gamma);
    k_init2<<<SIMS * NB / 256, 256>>>(ids);
    k_init3<<<1, 256>>>();
    k_init4<<<SIMS * NB / 256, 256>>>(ids);
    k_init5<<<NB, 128>>>(w2, gamma, beta, b2);
    k_base<<<G, TPB>>>(xs, w1, b1);

    const int smem_main = (RPC * MID + RPC * NB + MID + NB + NB + NB + 16) * 4
                        + (RPC * NB + NB + 1 + NB) * 4;
    cudaFuncSetAttribute(k_main, cudaFuncAttributeMaxDynamicSharedMemorySize, smem_main);
    k_main<<<G, TPB, smem_main>>>(xs, w1, out);
}

// round 4
// speedup vs baseline: 2.3608x; 1.1841x over previous
#include <cuda_runtime.h>
#include <math.h>

#define SIMS 2048
#define NB   256
#define MID  512
#define G    128     // persistent CTAs (1/SM)
#define TPB  512     // 16 warps -> 1 row per warp
#define RPC  16      // rows per CTA in k_main
#define GB   256     // k_base grid
#define RPCB 8       // rows per CTA in k_base

// ---------------- device scratch ----------------
__device__ __align__(16) float g_y [SIMS * MID];   // base = xs@w1+b1
__device__ __align__(16) float g_y2[SIMS * MID];   // base minus fw==0 columns
__device__ __align__(16) float g_w2g[NB * MID];    // gamma[j]*w2[j][c], c-major
__device__ __align__(16) float g_u[NB];            // current per-column value
__device__ __align__(16) float g_common[2 * MID];  // double-buffered common
__device__ float g_Ac[NB];                         // sum_j gamma*w2[:,c]
__device__ float g_bc[NB];                         // sum_j beta*w2[:,c] + b2[c]
__device__ int   g_winner[NB * NB];                // [t][c] = max s with ids[s,t]==c
__device__ int   g_fw[NB];
__device__ int   g_idsw[SIMS * NB];                // c | (winner-bit << 8)
__device__ int   g_newlist[NB];
__device__ int   g_newstart[NB + 1];
__device__ unsigned g_cnt;

// ---------------- grid barrier (monotonic counter) ----------------
__device__ __forceinline__ void gbar(unsigned &tgt) {
    __syncthreads();
    if (threadIdx.x == 0) {
        __threadfence();
        atomicAdd(&g_cnt, 1u);
        while (*(volatile unsigned*)&g_cnt < tgt) { }
        __threadfence();
    }
    __syncthreads();
    tgt += G;
}

// ---------------- fast erf-GELU (A&S 7.1.26, |err|<=1.5e-7) ----------------
__device__ __forceinline__ float gelu_f(float x) {
    float z  = 0.70710678118654752f * x;
    float az = fabsf(z);
    float t  = __fdividef(1.0f, fmaf(0.3275911f, az, 1.0f));
    float p  = t * fmaf(t, fmaf(t, fmaf(t, fmaf(t, 1.061405429f, -1.453152027f),
                                        1.421413741f), -0.284496736f), 0.254829592f);
    float ex = __expf(-z * z);
    float E  = fmaf(-p, ex, 1.0f);
    float e  = copysignf(E, x);
    float hx = 0.5f * x;
    return fmaf(hx, e, hx);
}

// ---------------- init kernels ----------------
__global__ void k_init1(const float* __restrict__ w2,
                        const float* __restrict__ gamma) {
    int idx = blockIdx.x * blockDim.x + threadIdx.x;   // 131072 threads
    if (idx < NB * NB) g_winner[idx] = -1;
    {   // w2g[c*MID + j] = gamma[j] * w2[j*NB + c]
        int c = idx >> 9, j = idx & (MID - 1);
        g_w2g[idx] = gamma[j] * w2[j * NB + c];
    }
    if (idx < 2 * MID) g_common[idx] = 0.f;
    if (idx < NB)      g_u[idx] = 0.f;
    if (idx == 0)      g_cnt = 0u;
}

__global__ void k_init2(const int* __restrict__ ids) {
    int idx = blockIdx.x * blockDim.x + threadIdx.x;   // idx = s*256 + t
    int s = idx >> 8;
    int t = idx & (NB - 1);
    int c = ids[idx];
    atomicMax(&g_winner[t * NB + c], s);
}

__global__ void k_init3() {
    __shared__ int fw[NB];
    __shared__ int cnt[NB];
    __shared__ int start[NB + 1];
    __shared__ int offs[NB];
    int c = threadIdx.x;                 // 256 threads
    cnt[c] = 0;
    int f = 1 << 30;
    for (int t = 0; t < NB; t++)
        if (g_winner[t * NB + c] >= 0) { f = t; break; }
    g_fw[c] = f;
    fw[c] = f;
    __syncthreads();
    if (f < NB) atomicAdd(&cnt[f], 1);
    __syncthreads();
    if (c == 0) {
        int pos = 0;
        for (int t = 0; t < NB; t++) { start[t] = pos; pos += cnt[t]; }
        start[NB] = pos;
    }
    __syncthreads();
    g_newstart[c] = start[c];
    if (c == 0) g_newstart[NB] = start[NB];
    offs[c] = start[c];
    __syncthreads();
    if (f < NB) {
        int p = atomicAdd(&offs[f], 1);
        g_newlist[p] = c;
    }
}

__global__ void k_init4(const int* __restrict__ ids) {
    int idx = blockIdx.x * blockDim.x + threadIdx.x;   // idx = s*256 + t
    int s = idx >> 8;
    int t = idx & (NB - 1);
    int c = ids[idx];
    int win = (g_winner[t * NB + c] == s) ? 256 : 0;
    g_idsw[idx] = c | win;
}

__global__ void k_init5(const float* __restrict__ w2,
                        const float* __restrict__ gamma,
                        const float* __restrict__ beta,
                        const float* __restrict__ b2) {
    __shared__ float sa[4], sb[4];
    int c = blockIdx.x;
    int tid = threadIdx.x;               // 128 threads
    float a = 0.f, bs = 0.f;
    for (int j = tid; j < MID; j += 128) {
        float w = w2[j * NB + c];
        a  = fmaf(gamma[j], w, a);
        bs = fmaf(beta[j],  w, bs);
    }
#pragma unroll
    for (int off = 16; off; off >>= 1) {
        a  += __shfl_xor_sync(0xffffffffu, a,  off);
        bs += __shfl_xor_sync(0xffffffffu, bs, off);
    }
    if ((tid & 31) == 0) { sa[tid >> 5] = a; sb[tid >> 5] = bs; }
    __syncthreads();
    if (tid == 0) {
        g_Ac[c] = sa[0] + sa[1] + sa[2] + sa[3];
        g_bc[c] = sb[0] + sb[1] + sb[2] + sb[3] + b2[c];
    }
}

// base = xs @ w1 + b1 ; y2 = b1 + sum over columns with fw>=1
__global__ void __launch_bounds__(TPB) k_base(const float* __restrict__ xs,
                                              const float* __restrict__ w1,
                                              const float* __restrict__ b1) {
    __shared__ float xsS[RPCB * NB];
    int tid = threadIdx.x;               // j = tid
    int row0 = blockIdx.x * RPCB;
    for (int i = tid; i < RPCB * NB; i += TPB) xsS[i] = xs[row0 * NB + i];
    __syncthreads();

    float acc[RPCB];
#pragma unroll
    for (int r = 0; r < RPCB; r++) acc[r] = 0.f;
#pragma unroll 8
    for (int c = 0; c < NB; c++) {
        float w = w1[c * MID + tid];
#pragma unroll
        for (int r = 0; r < RPCB; r++)
            acc[r] = fmaf(xsS[r * NB + c], w, acc[r]);
    }
    float bb = b1[tid];
#pragma unroll
    for (int r = 0; r < RPCB; r++)
        g_y[(row0 + r) * MID + tid] = acc[r] + bb;

    float y2a[RPCB];
#pragma unroll
    for (int r = 0; r < RPCB; r++) y2a[r] = bb;
    int st = g_newstart[1], en = g_newstart[NB];
    for (int i = st; i < en; i++) {
        int c = g_newlist[i];
        float w = w1[c * MID + tid];
#pragma unroll
        for (int r = 0; r < RPCB; r++)
            y2a[r] = fmaf(xsS[r * NB + c], w, y2a[r]);
    }
#pragma unroll
    for (int r = 0; r < RPCB; r++)
        g_y2[(row0 + r) * MID + tid] = y2a[r];
}

// ---------------- main persistent kernel ----------------
__global__ void __launch_bounds__(TPB) k_main(const float* __restrict__ xs,
                                              const float* __restrict__ w1,
                                              float* __restrict__ out) {
    extern __shared__ float sm[];
    float* yS    = sm;                        // 8192
    float* xsS   = yS + RPC * MID;            // 4096
    float* cS    = xsS + RPC * NB;            // 512
    float* AcS   = cS + MID;                  // 256
    float* bcS   = AcS + NB;                  // 256
    float* dS    = bcS + NB;                  // 16  (winner deltas)
    int*   colS  = (int*)(dS + 16);           // 16
    int*   flagS = colS + 16;                 // 16
    int*   idswS = flagS + 16;                // 4096
    int*   nsS   = idswS + RPC * NB;          // 257
    int*   fwS   = nsS + (NB + 1);            // 256
    float* uS    = (float*)(fwS + NB);        // 256 (final output stage)

    const int tid  = threadIdx.x;
    const int b    = blockIdx.x;
    const int row0 = b * RPC;
    const int lane = tid & 31;
    const int wid  = tid >> 5;                // row within CTA (0..15)

    for (int i = tid; i < RPC * MID; i += TPB) yS[i] = g_y[row0 * MID + i];
    for (int i = tid; i < RPC * NB; i += TPB) {
        xsS[i]   = xs[row0 * NB + i];
        idswS[i] = g_idsw[row0 * NB + i];
    }
    if (tid < NB) {
        AcS[tid] = g_Ac[tid];
        bcS[tid] = g_bc[tid];
        fwS[tid] = g_fw[tid];
    }
    if (tid <= NB) nsS[tid] = g_newstart[tid];
    __syncthreads();

    unsigned tgt = G;
    float rprev = 0.f;                        // this CTA's delta[tid] from step t-1

    for (int t = 0; t < NB; t++) {
        float* bufR = g_common + ((t & 1) << 9);
        float* bufW = g_common + (((t + 1) & 1) << 9);

        cS[tid] = bufR[tid];
        __syncthreads();

        // ---- phase A: one row per warp ----
        {
            const int rl = wid;
            int info = idswS[rl * NB + t];
            int col  = info & 255;
            int win  = info & 256;
            float uold = win ? g_u[col] : 0.f;   // prefetch before heavy pass
            const float4* y4 = (const float4*)(yS + rl * MID);
            const float4* c4 = (const float4*)cS;
            const float4* w4 = (const float4*)(g_w2g + (size_t)col * MID);
            float s = 0.f, q = 0.f, d = 0.f;
#pragma unroll
            for (int k = 0; k < 4; k++) {
                float4 yv = y4[k * 32 + lane];
                float4 cv = c4[k * 32 + lane];
                float4 wv = w4[k * 32 + lane];
                float g0 = gelu_f(yv.x + cv.x);
                float g1 = gelu_f(yv.y + cv.y);
                float g2 = gelu_f(yv.z + cv.z);
                float g3 = gelu_f(yv.w + cv.w);
                s += (g0 + g1) + (g2 + g3);
                q = fmaf(g0, g0, q); q = fmaf(g1, g1, q);
                q = fmaf(g2, g2, q); q = fmaf(g3, g3, q);
                d = fmaf(g0, wv.x, d); d = fmaf(g1, wv.y, d);
                d = fmaf(g2, wv.z, d); d = fmaf(g3, wv.w, d);
            }
#pragma unroll
            for (int off = 16; off; off >>= 1) {
                s += __shfl_xor_sync(0xffffffffu, s, off);
                q += __shfl_xor_sync(0xffffffffu, q, off);
                d += __shfl_xor_sync(0xffffffffu, d, off);
            }
            if (lane == 0) {
                flagS[rl] = win;
                colS[rl]  = col;
                if (win) {
                    float mu  = s * (1.f / 512.f);
                    float var = fmaf(-mu, mu, q * (1.f / 512.f));
                    float inv = rsqrtf(var + 1e-5f);
                    float logit = fmaf(inv, fmaf(-mu, AcS[col], d), bcS[col]);
                    float p = __fdividef(1.f, 1.f + __expf(-logit));
                    g_u[col] = p;
                    dS[rl] = p - uold;
                }
            }
        }
        __syncthreads();

        // ---- local delta of common: r = sum over this CTA's winners ----
        {
            float r = 0.f;
#pragma unroll
            for (int w = 0; w < RPC; w++) {
                if (flagS[w]) {
                    float wv = w1[colS[w] * MID + tid];
                    r = fmaf(dS[w], wv, r);
                }
            }
            float add = r + rprev;        // this step's delta + last step's delta
            rprev = r;
            atomicAdd(&bufW[tid], add);   // buf[(t+1)&1] becomes common(t+1)
        }

        // ---- first-write corrections (CTA-local) ----
        if (t == 0) {
            for (int i = tid; i < RPC * MID; i += TPB)
                yS[i] = g_y2[row0 * MID + i];
        } else {
            int st = nsS[t], en = nsS[t + 1];
            for (int i = st; i < en; i++) {
                int c = g_newlist[i];
                float w = w1[c * MID + tid];
#pragma unroll
                for (int rl = 0; rl < RPC; rl++)
                    yS[rl * MID + tid] -= xsS[rl * NB + c] * w;
            }
        }

        gbar(tgt);   // single barrier: u(t), delta-adds, all visible
    }

    // ---- output: u[c] if ever written else xs ----
    if (tid < NB) uS[tid] = g_u[tid];
    __syncthreads();
    for (int i = tid; i < RPC * NB; i += TPB) {
        int c  = i & (NB - 1);
        int rl = i >> 8;
        float v = (fwS[c] < NB) ? uS[c] : xsS[i];
        out[(row0 + rl) * NB + c] = v;
    }
}

// ---------------- launch ----------------
extern "C" void kernel_launch(void* const* d_in, const int* in_sizes, int n_in,
                              void* d_out, int out_size) {
    const float* xs    = (const float*)d_in[0];
    const int*   ids   = (const int*)d_in[1];
    const float* w1    = (const float*)d_in[2];
    const float* b1    = (const float*)d_in[3];
    const float* gamma = (const float*)d_in[4];
    const float* beta  = (const float*)d_in[5];
    const float* w2    = (const float*)d_in[6];
    const float* b2    = (const float*)d_in[7];
    float* out = (float*)d_out;

    k_init1<<<512, 256>>>(w2, gamma);
    k_init2<<<SIMS * NB / 256, 256>>>(ids);
    k_init3<<<1, 256>>>();
    k_init4<<<SIMS * NB / 256, 256>>>(ids);
    k_init5<<<NB, 128>>>(w2, gamma, beta, b2);
    k_base<<<GB, TPB>>>(xs, w1, b1);

    const int smem_main = (RPC * MID + RPC * NB + MID + NB + NB + 16) * 4
                        + (16 + 16 + RPC * NB + NB + 1 + NB) * 4 + NB * 4;
    cudaFuncSetAttribute(k_main, cudaFuncAttributeMaxDynamicSharedMemorySize, smem_main);
    k_main<<<G, TPB, smem_main>>>(xs, w1, out);
}

// round 5
// speedup vs baseline: 3.2017x; 1.3562x over previous
#include <cuda_runtime.h>
#include <math.h>

#define SIMS 2048
#define NB   256
#define MID  512
#define G    128     // persistent CTAs
#define TPB  512
#define RPC  16      // rows per CTA (output ownership)
#define GB   256     // k_base grid
#define RPCB 8
#define CSTR 32      // floats between common groups (128B line stride)
#define NGRP 128     // 128 float4-groups = 512 floats

// ---------------- device scratch ----------------
__device__ __align__(16) float g_y [SIMS * MID];       // base = xs@w1+b1
__device__ __align__(16) float g_y2[SIMS * MID];       // base minus fw==0 cols
__device__ __align__(16) float g_w2g[NB * MID];        // gamma[j]*w2[j][c], c-major
__device__ __align__(16) float g_u[NB];
__device__ __align__(16) float g_commonX[2 * NGRP * CSTR]; // strided dbl-buffer
__device__ float g_Ac[NB];
__device__ float g_bc[NB];
__device__ int   g_winner[NB * NB];                    // [t][c] = max s, else -1
__device__ int   g_fw[NB];
__device__ int   g_tasks[NB * NB];                     // [t][i] = (s<<8)|c, -1 pad
__device__ int   g_newlist[NB];
__device__ int   g_newstart[NB + 1];
__device__ unsigned g_cnt;

// ---------------- grid barrier (monotonic counter) ----------------
__device__ __forceinline__ void gbar(unsigned &tgt) {
    __syncthreads();
    if (threadIdx.x == 0) {
        __threadfence();
        atomicAdd(&g_cnt, 1u);
        while (*(volatile unsigned*)&g_cnt < tgt) { }
        __threadfence();
    }
    __syncthreads();
    tgt += G;
}

// ---------------- fast erf-GELU (A&S 7.1.26, |err|<=1.5e-7) ----------------
__device__ __forceinline__ float gelu_f(float x) {
    float z  = 0.70710678118654752f * x;
    float az = fabsf(z);
    float t  = __fdividef(1.0f, fmaf(0.3275911f, az, 1.0f));
    float p  = t * fmaf(t, fmaf(t, fmaf(t, fmaf(t, 1.061405429f, -1.453152027f),
                                        1.421413741f), -0.284496736f), 0.254829592f);
    float ex = __expf(-z * z);
    float E  = fmaf(-p, ex, 1.0f);
    float e  = copysignf(E, x);
    float hx = 0.5f * x;
    return fmaf(hx, e, hx);
}

// ---------------- init kernels ----------------
__global__ void k_init1(const float* __restrict__ w2,
                        const float* __restrict__ gamma) {
    int idx = blockIdx.x * blockDim.x + threadIdx.x;   // 131072 threads
    if (idx < NB * NB) g_winner[idx] = -1;
    {   // w2g[c*MID + j] = gamma[j] * w2[j*NB + c]
        int c = idx >> 9, j = idx & (MID - 1);
        g_w2g[idx] = gamma[j] * w2[j * NB + c];
    }
    if (idx < 2 * NGRP * CSTR) g_commonX[idx] = 0.f;
    if (idx < NB)  g_u[idx] = 0.f;
    if (idx == 0)  g_cnt = 0u;
}

__global__ void k_init2(const int* __restrict__ ids) {
    int idx = blockIdx.x * blockDim.x + threadIdx.x;   // idx = s*256 + t
    int s = idx >> 8;
    int t = idx & (NB - 1);
    int c = ids[idx];
    atomicMax(&g_winner[t * NB + c], s);
}

__global__ void k_init3() {
    __shared__ int fw[NB];
    __shared__ int cnt[NB];
    __shared__ int start[NB + 1];
    __shared__ int offs[NB];
    int c = threadIdx.x;                 // 256 threads
    cnt[c] = 0;
    int f = 1 << 30;
    for (int t = 0; t < NB; t++)
        if (g_winner[t * NB + c] >= 0) { f = t; break; }
    g_fw[c] = f;
    fw[c] = f;
    __syncthreads();
    if (f < NB) atomicAdd(&cnt[f], 1);
    __syncthreads();
    if (c == 0) {
        int pos = 0;
        for (int t = 0; t < NB; t++) { start[t] = pos; pos += cnt[t]; }
        start[NB] = pos;
    }
    __syncthreads();
    g_newstart[c] = start[c];
    if (c == 0) g_newstart[NB] = start[NB];
    offs[c] = start[c];
    __syncthreads();
    if (f < NB) {
        int p = atomicAdd(&offs[f], 1);
        g_newlist[p] = c;
    }
}

// deterministic compacted task list per step
__global__ void k_task() {
    __shared__ int wcnt[8];
    int t = blockIdx.x, c = threadIdx.x;   // 256 threads
    int s = g_winner[t * NB + c];
    int valid = (s >= 0);
    unsigned mask = __ballot_sync(0xffffffffu, valid);
    int w = c >> 5, lane = c & 31;
    if (lane == 0) wcnt[w] = __popc(mask);
    g_tasks[t * NB + c] = -1;
    __syncthreads();
    int base = 0;
    for (int k = 0; k < w; k++) base += wcnt[k];
    if (valid) {
        int pos = base + __popc(mask & ((1u << lane) - 1u));
        g_tasks[t * NB + pos] = (s << 8) | c;
    }
}

__global__ void k_init5(const float* __restrict__ w2,
                        const float* __restrict__ gamma,
                        const float* __restrict__ beta,
                        const float* __restrict__ b2) {
    __shared__ float sa[4], sb[4];
    int c = blockIdx.x;
    int tid = threadIdx.x;               // 128 threads
    float a = 0.f, bs = 0.f;
    for (int j = tid; j < MID; j += 128) {
        float w = w2[j * NB + c];
        a  = fmaf(gamma[j], w, a);
        bs = fmaf(beta[j],  w, bs);
    }
#pragma unroll
    for (int off = 16; off; off >>= 1) {
        a  += __shfl_xor_sync(0xffffffffu, a,  off);
        bs += __shfl_xor_sync(0xffffffffu, bs, off);
    }
    if ((tid & 31) == 0) { sa[tid >> 5] = a; sb[tid >> 5] = bs; }
    __syncthreads();
    if (tid == 0) {
        g_Ac[c] = sa[0] + sa[1] + sa[2] + sa[3];
        g_bc[c] = sb[0] + sb[1] + sb[2] + sb[3] + b2[c];
    }
}

// base = xs@w1 + b1 ; y2 = b1 + columns with fw>=1
__global__ void __launch_bounds__(TPB) k_base(const float* __restrict__ xs,
                                              const float* __restrict__ w1,
                                              const float* __restrict__ b1) {
    __shared__ float xsS[RPCB * NB];
    int tid = threadIdx.x;
    int row0 = blockIdx.x * RPCB;
    for (int i = tid; i < RPCB * NB; i += TPB) xsS[i] = xs[row0 * NB + i];
    __syncthreads();

    float acc[RPCB];
#pragma unroll
    for (int r = 0; r < RPCB; r++) acc[r] = 0.f;
#pragma unroll 8
    for (int c = 0; c < NB; c++) {
        float w = w1[c * MID + tid];
#pragma unroll
        for (int r = 0; r < RPCB; r++)
            acc[r] = fmaf(xsS[r * NB + c], w, acc[r]);
    }
    float bb = b1[tid];
#pragma unroll
    for (int r = 0; r < RPCB; r++)
        g_y[(row0 + r) * MID + tid] = acc[r] + bb;

    float y2a[RPCB];
#pragma unroll
    for (int r = 0; r < RPCB; r++) y2a[r] = bb;
    int st = g_newstart[1], en = g_newstart[NB];
    for (int i = st; i < en; i++) {
        int c = g_newlist[i];
        float w = w1[c * MID + tid];
#pragma unroll
        for (int r = 0; r < RPCB; r++)
            y2a[r] = fmaf(xsS[r * NB + c], w, y2a[r]);
    }
#pragma unroll
    for (int r = 0; r < RPCB; r++)
        g_y2[(row0 + r) * MID + tid] = y2a[r];
}

// ---------------- main persistent kernel ----------------
__global__ void __launch_bounds__(TPB) k_main(const float* __restrict__ xs,
                                              const float* __restrict__ w1,
                                              float* __restrict__ out) {
    __shared__ float cS[MID];
    __shared__ float sred[2 * 8 * 3];
    __shared__ float dval[2];
    __shared__ int   dcol[2];
    __shared__ int   taskS[2 * NB];
    __shared__ int   nsS[NB + 1];
    __shared__ float uS[NB];
    __shared__ int   fwS[NB];

    const int tid  = threadIdx.x;
    const int b    = blockIdx.x;
    const int row0 = b * RPC;
    const int lane = tid & 31;
    const int grp  = tid >> 8;                // 0 / 1 (task group)
    const int gtid = tid & 255;
    const int gw   = (tid >> 5) & 7;          // warp within group

    // preload this CTA's 2 tasks for every step
    for (int i = tid; i < 2 * NB; i += TPB) {
        int t = i >> 1, k = i & 1;
        taskS[i] = g_tasks[t * NB + 2 * b + k];
    }
    if (tid <= NB) nsS[tid] = g_newstart[tid];
    if (tid < NB)  fwS[tid] = g_fw[tid];
    __syncthreads();

    unsigned tgt = G;
    float4 rprev = make_float4(0.f, 0.f, 0.f, 0.f);

    for (int t = 0; t < NB; t++) {
        if (tid < 2) dcol[tid] = -1;
        if (tid < NGRP) {
            float4 cv = *(const float4*)&g_commonX[(t & 1) * (NGRP * CSTR) + tid * CSTR];
            ((float4*)cS)[tid] = cv;
        }
        int task = taskS[t * 2 + grp];
        const float* yb = (t == 0) ? g_y : g_y2;
        __syncthreads();

        // ---- phase A: up to 2 winner rows, 8 warps each ----
        int c = 0;
        float uold = 0.f;
        if (task >= 0) {
            c = task & 255;
            int srow = task >> 8;
            uold = g_u[c];
            float2 yv = ((const float2*)(yb + (size_t)srow * MID))[gtid];
            float2 cv = ((const float2*)cS)[gtid];
            float2 wv = ((const float2*)(g_w2g + (size_t)c * MID))[gtid];
            float g0 = gelu_f(yv.x + cv.x);
            float g1 = gelu_f(yv.y + cv.y);
            float s = g0 + g1;
            float q = fmaf(g0, g0, g1 * g1);
            float d = fmaf(g0, wv.x, g1 * wv.y);
#pragma unroll
            for (int off = 16; off; off >>= 1) {
                s += __shfl_xor_sync(0xffffffffu, s, off);
                q += __shfl_xor_sync(0xffffffffu, q, off);
                d += __shfl_xor_sync(0xffffffffu, d, off);
            }
            if (lane == 0) {
                sred[(grp * 8 + gw) * 3 + 0] = s;
                sred[(grp * 8 + gw) * 3 + 1] = q;
                sred[(grp * 8 + gw) * 3 + 2] = d;
            }
        }
        __syncthreads();

        if (gtid == 0 && task >= 0) {
            float S = 0.f, Q = 0.f, D = 0.f;
#pragma unroll
            for (int k = 0; k < 8; k++) {
                S += sred[(grp * 8 + k) * 3 + 0];
                Q += sred[(grp * 8 + k) * 3 + 1];
                D += sred[(grp * 8 + k) * 3 + 2];
            }
            float mu  = S * (1.f / 512.f);
            float var = fmaf(-mu, mu, Q * (1.f / 512.f));
            float inv = rsqrtf(var + 1e-5f);
            float logit = fmaf(inv, fmaf(-mu, g_Ac[c], D), g_bc[c]);
            float p = __fdividef(1.f, 1.f + __expf(-logit));
            g_u[c] = p;
            dval[grp] = p - uold;
            dcol[grp] = c;
        }
        __syncthreads();

        // ---- delta of common: vector RED into strided buffer ----
        if (tid < NGRP) {
            float4 r = make_float4(0.f, 0.f, 0.f, 0.f);
#pragma unroll
            for (int k = 0; k < 2; k++) {
                int cc = dcol[k];
                if (cc >= 0) {
                    float dd = dval[k];
                    float4 wv = ((const float4*)(w1 + (size_t)cc * MID))[tid];
                    r.x = fmaf(dd, wv.x, r.x);
                    r.y = fmaf(dd, wv.y, r.y);
                    r.z = fmaf(dd, wv.z, r.z);
                    r.w = fmaf(dd, wv.w, r.w);
                }
            }
            float4 add = make_float4(r.x + rprev.x, r.y + rprev.y,
                                     r.z + rprev.z, r.w + rprev.w);
            rprev = r;
            atomicAdd((float4*)&g_commonX[((t + 1) & 1) * (NGRP * CSTR) + tid * CSTR], add);
        }

        // ---- rare first-write corrections for t>=1 ----
        if (t > 0) {
            int st = nsS[t], en = nsS[t + 1];
            for (int i = st; i < en; i++) {
                int cc = g_newlist[i];
                float w = w1[cc * MID + tid];
                for (int rl = 0; rl < RPC; rl++) {
                    float xv = xs[(row0 + rl) * NB + cc];
                    g_y2[(size_t)(row0 + rl) * MID + tid] -= xv * w;
                }
            }
        }

        gbar(tgt);   // one barrier: g_u, RED-adds, y2 corrections all visible
    }

    // ---- output ----
    if (tid < NB) uS[tid] = g_u[tid];
    __syncthreads();
    for (int i = tid; i < RPC * NB; i += TPB) {
        int c2 = i & (NB - 1);
        int rl = i >> 8;
        float v = (fwS[c2] < NB) ? uS[c2] : xs[(row0 + rl) * NB + c2];
        out[(row0 + rl) * NB + c2] = v;
    }
}

// ---------------- launch ----------------
extern "C" void kernel_launch(void* const* d_in, const int* in_sizes, int n_in,
                              void* d_out, int out_size) {
    const float* xs    = (const float*)d_in[0];
    const int*   ids   = (const int*)d_in[1];
    const float* w1    = (const float*)d_in[2];
    const float* b1    = (const float*)d_in[3];
    const float* gamma = (const float*)d_in[4];
    const float* beta  = (const float*)d_in[5];
    const float* w2    = (const float*)d_in[6];
    const float* b2    = (const float*)d_in[7];
    float* out = (float*)d_out;

    k_init1<<<512, 256>>>(w2, gamma);
    k_init2<<<SIMS * NB / 256, 256>>>(ids);
    k_init3<<<1, 256>>>();
    k_task<<<NB, 256>>>();
    k_init5<<<NB, 128>>>(w2, gamma, beta, b2);
    k_base<<<GB, TPB>>>(xs, w1, b1);
    k_main<<<G, TPB>>>(xs, w1, out);
}